// round 1
// baseline (speedup 1.0000x reference)
#include <cuda_runtime.h>
#include <math.h>

#define NBATCH 8
#define NPTS   256
#define NFEAT  32
#define NRBF_  50
#define NH     128
#define NK     255          // NPTS-1
#define SD     8960         // NPTS*3 + NPTS*32

// scratch (no allocations allowed)
__device__ float g_vx[NBATCH * NPTS * 3];
__device__ float g_tr[NBATCH * NPTS];

// ---- shared memory layout (floats) ----
#define O_W1S1 0                     // 50*128 s1_W1 rbf block
#define O_W1SM (O_W1S1 + 6400)      // mu[m]*s1_W1
#define O_W1S2 (O_W1SM + 6400)      // s2_W1 rbf block
#define O_W1SF (O_W1S2 + 6400)      // f_W1 rbf block
#define O_FW2  (O_W1SF + 6400)      // 128*32
#define O_W2S1 (O_FW2 + 4096)       // 128
#define O_W2S2 (O_W2S1 + 128)       // 128
#define O_CF1  (O_W2S2 + 128)       // 128
#define O_CF2  (O_CF1 + 128)        // 128
#define O_CFF  (O_CF2 + 128)        // 128
#define O_XS   (O_CFF + 128)        // 768 positions
#define O_FS   (O_XS + 768)         // 32 feats
#define O_SMX  (O_FS + 32)          // 32 softmax(feats)
#define O_MUS  (O_SMX + 32)         // 64 (50 used)
#define O_RED  (O_MUS + 64)         // 8*40 reduction scratch
#define O_TOT  (O_RED + 320)        // 40 totals
#define SMEM_FLOATS (O_TOT + 40)

// per-hidden-lane epilogue
#define EPILOGUE(A1, AM, A2, AF, C1, C2, CF, W21, W22, HIDX) do {            \
    float z1 = (A1) + (C1);                                                  \
    float sg1 = __fdividef(1.f, 1.f + __expf(-z1));                          \
    s1a = fmaf(z1 * sg1, (W21), s1a);                                        \
    float sp = sg1 * (1.f + z1 * (1.f - sg1));                               \
    da = fmaf((W21) * sp, fmaf(dloc, (A1), -(AM)), da);                      \
    float z2 = (A2) + (C2);                                                  \
    float sg2 = __fdividef(1.f, 1.f + __expf(-z2));                          \
    s2a = fmaf(z2 * sg2, (W22), s2a);                                        \
    float zf = (AF) + (CF);                                                  \
    float sgf = __fdividef(1.f, 1.f + __expf(-zf));                          \
    float slf = zf * sgf;                                                    \
    {                                                                        \
      const float* fwrow = &smf[O_FW2 + (HIDX) * 32];                        \
      _Pragma("unroll")                                                      \
      for (int ff = 0; ff < 32; ff += 4) {                                   \
        const float4 wv = *reinterpret_cast<const float4*>(&fwrow[ff]);      \
        vf[ff + 0] = fmaf(slf, wv.x, vf[ff + 0]);                            \
        vf[ff + 1] = fmaf(slf, wv.y, vf[ff + 1]);                            \
        vf[ff + 2] = fmaf(slf, wv.z, vf[ff + 2]);                            \
        vf[ff + 3] = fmaf(slf, wv.w, vf[ff + 3]);                            \
      }                                                                      \
    }                                                                        \
  } while (0)

__global__ __launch_bounds__(256, 1) void fd_main(
    const float* __restrict__ state, const float* __restrict__ mus,
    const float* __restrict__ gamma_p,
    const float* __restrict__ s1W1, const float* __restrict__ s1b1,
    const float* __restrict__ s1W2, const float* __restrict__ s1b2,
    const float* __restrict__ s2W1, const float* __restrict__ s2b1,
    const float* __restrict__ s2W2, const float* __restrict__ s2b2,
    const float* __restrict__ fW1, const float* __restrict__ fb1,
    const float* __restrict__ fW2, const float* __restrict__ fb2,
    float* __restrict__ out)
{
  extern __shared__ float smf[];
  const int tid = threadIdx.x;
  const int bi = blockIdx.x;
  const int b = bi >> 8;
  const int i = bi & 255;
  const float gam = gamma_p[0];

  // --- stage weights / inputs into smem ---
  for (int idx = tid; idx < 6400; idx += 256) {
    float w = s1W1[idx];
    smf[O_W1S1 + idx] = w;
    smf[O_W1SM + idx] = w * mus[idx >> 7];
    smf[O_W1S2 + idx] = s2W1[idx];
    smf[O_W1SF + idx] = fW1[idx];
  }
  for (int idx = tid; idx < 4096; idx += 256) smf[O_FW2 + idx] = fW2[idx];
  if (tid < 128) {
    smf[O_W2S1 + tid] = s1W2[tid];
    smf[O_W2S2 + tid] = s2W2[tid];
  }
  for (int idx = tid; idx < 768; idx += 256) smf[O_XS + idx] = state[b * SD + idx];
  if (tid < 32) smf[O_FS + tid] = state[b * SD + 768 + i * 32 + tid];
  if (tid < 64) smf[O_MUS + tid] = (tid < NRBF_) ? mus[tid] : 0.f;
  __syncthreads();

  // softmax(feats) by warp 0
  if (tid < 32) {
    float v = smf[O_FS + tid];
    float mx = v;
    #pragma unroll
    for (int o = 16; o; o >>= 1) mx = fmaxf(mx, __shfl_xor_sync(0xffffffffu, mx, o));
    float e = __expf(v - mx);
    float s = e;
    #pragma unroll
    for (int o = 16; o; o >>= 1) s += __shfl_xor_sync(0xffffffffu, s, o);
    smf[O_SMX + tid] = __fdividef(e, s);
  }
  __syncthreads();

  // per-(b,i) constant hidden contributions (feat columns + bias)
  if (tid < 128) {
    const int h = tid;
    float c1 = s1b1[h], c2 = s2b1[h], cf = fb1[h];
    #pragma unroll 4
    for (int f = 0; f < 32; f++) {
      float fv = smf[O_FS + f];
      c1 = fmaf(fv, s1W1[(50 + f) * 128 + h] + s1W1[(82 + f) * 128 + h], c1);
      c2 = fmaf(fv, s2W1[(50 + f) * 128 + h] + s2W1[(82 + f) * 128 + h], c2);
      cf = fmaf(smf[O_SMX + f], fW1[(50 + f) * 128 + h], cf);
    }
    smf[O_CF1 + h] = c1;
    smf[O_CF2 + h] = c2;
    smf[O_CFF + h] = cf;
  }
  __syncthreads();

  // --- per-neighbor compute: thread tid handles k = tid ---
  float s1rx = 0.f, s1ry = 0.f, s1rz = 0.f;
  float s2rx = 0.f, s2ry = 0.f, s2rz = 0.f;
  float trc = 0.f;
  float vf[32];
  #pragma unroll
  for (int f = 0; f < 32; f++) vf[f] = 0.f;

  if (tid < NK) {
    const int k = tid;
    const int j = (k < i) ? k : k + 1;
    const float rx = smf[O_XS + i * 3 + 0] - smf[O_XS + j * 3 + 0];
    const float ry = smf[O_XS + i * 3 + 1] - smf[O_XS + j * 3 + 1];
    const float rz = smf[O_XS + i * 3 + 2] - smf[O_XS + j * 3 + 2];
    const float rr2 = rx * rx + ry * ry + rz * rz;
    const float dloc = sqrtf(rr2 + 1e-6f);

    float rbf[NRBF_];
    #pragma unroll
    for (int m = 0; m < NRBF_; m++) {
      float dm = dloc - smf[O_MUS + m];
      rbf[m] = __expf(-gam * dm * dm);
    }

    float s1a = 0.f, s2a = 0.f, da = 0.f;

    #pragma unroll 1
    for (int hb = 0; hb < 128; hb += 4) {
      float a1x = 0.f, a1y = 0.f, a1z = 0.f, a1w = 0.f;
      float amx = 0.f, amy = 0.f, amz = 0.f, amw = 0.f;
      float a2x = 0.f, a2y = 0.f, a2z = 0.f, a2w = 0.f;
      float afx = 0.f, afy = 0.f, afz = 0.f, afw = 0.f;
      #pragma unroll
      for (int m = 0; m < NRBF_; m++) {
        const float rv = rbf[m];
        const float4 w1 = *reinterpret_cast<const float4*>(&smf[O_W1S1 + m * 128 + hb]);
        a1x = fmaf(rv, w1.x, a1x); a1y = fmaf(rv, w1.y, a1y);
        a1z = fmaf(rv, w1.z, a1z); a1w = fmaf(rv, w1.w, a1w);
        const float4 wm = *reinterpret_cast<const float4*>(&smf[O_W1SM + m * 128 + hb]);
        amx = fmaf(rv, wm.x, amx); amy = fmaf(rv, wm.y, amy);
        amz = fmaf(rv, wm.z, amz); amw = fmaf(rv, wm.w, amw);
        const float4 w2 = *reinterpret_cast<const float4*>(&smf[O_W1S2 + m * 128 + hb]);
        a2x = fmaf(rv, w2.x, a2x); a2y = fmaf(rv, w2.y, a2y);
        a2z = fmaf(rv, w2.z, a2z); a2w = fmaf(rv, w2.w, a2w);
        const float4 wf = *reinterpret_cast<const float4*>(&smf[O_W1SF + m * 128 + hb]);
        afx = fmaf(rv, wf.x, afx); afy = fmaf(rv, wf.y, afy);
        afz = fmaf(rv, wf.z, afz); afw = fmaf(rv, wf.w, afw);
      }
      const float4 c1v = *reinterpret_cast<const float4*>(&smf[O_CF1 + hb]);
      const float4 c2v = *reinterpret_cast<const float4*>(&smf[O_CF2 + hb]);
      const float4 cfv = *reinterpret_cast<const float4*>(&smf[O_CFF + hb]);
      const float4 w21 = *reinterpret_cast<const float4*>(&smf[O_W2S1 + hb]);
      const float4 w22 = *reinterpret_cast<const float4*>(&smf[O_W2S2 + hb]);
      EPILOGUE(a1x, amx, a2x, afx, c1v.x, c2v.x, cfv.x, w21.x, w22.x, hb + 0);
      EPILOGUE(a1y, amy, a2y, afy, c1v.y, c2v.y, cfv.y, w21.y, w22.y, hb + 1);
      EPILOGUE(a1z, amz, a2z, afz, c1v.z, c2v.z, cfv.z, w21.z, w22.z, hb + 2);
      EPILOGUE(a1w, amw, a2w, afw, c1v.w, c2v.w, cfv.w, w21.w, w22.w, hb + 3);
    }

    s1a += s1b2[0];
    s2a += s2b2[0];
    // gd = ds1/dd * r2d ;  ds1/dd = -2*gamma * sum_h W2[h]*silu'(z1_h)*(d*a1_h - am_h)
    const float gd = -2.f * gam * da * __fdividef(rr2, dloc);
    s1rx = s1a * rx; s1ry = s1a * ry; s1rz = s1a * rz;
    s2rx = s2a * rx; s2ry = s2a * ry; s2rz = s2a * rz;
    trc = gd + 3.f * s1a;
  }

  // --- block reduction over neighbors (39 values) ---
  float vals[39];
  vals[0] = s1rx; vals[1] = s1ry; vals[2] = s1rz;
  vals[3] = s2rx; vals[4] = s2ry; vals[5] = s2rz;
  vals[6] = trc;
  #pragma unroll
  for (int f = 0; f < 32; f++) vals[7 + f] = vf[f];

  #pragma unroll
  for (int c = 0; c < 39; c++) {
    float v = vals[c];
    #pragma unroll
    for (int o = 16; o; o >>= 1) v += __shfl_xor_sync(0xffffffffu, v, o);
    vals[c] = v;
  }
  const int wid = tid >> 5, lane = tid & 31;
  if (lane == 0) {
    #pragma unroll
    for (int c = 0; c < 39; c++) smf[O_RED + wid * 40 + c] = vals[c];
  }
  __syncthreads();
  if (tid < 39) {
    float s = 0.f;
    #pragma unroll
    for (int w = 0; w < 8; w++) s += smf[O_RED + w * 40 + tid];
    smf[O_TOT + tid] = s;
  }
  __syncthreads();

  if (tid == 0) {
    const float inv = 1.f / (float)NK;
    const float v1x = smf[O_TOT + 0] * inv;
    const float v1y = smf[O_TOT + 1] * inv;
    const float v1z = smf[O_TOT + 2] * inv;
    const float m2x = smf[O_TOT + 3] * inv;
    const float m2y = smf[O_TOT + 4] * inv;
    const float m2z = smf[O_TOT + 5] * inv;
    // mean_k( s2 * (r x v1) ) = (mean_k s2*r) x v1
    const float cxx = m2y * v1z - m2z * v1y;
    const float cxy = m2z * v1x - m2x * v1z;
    const float cxz = m2x * v1y - m2y * v1x;
    g_vx[bi * 3 + 0] = v1x + cxx;
    g_vx[bi * 3 + 1] = v1y + cxy;
    g_vx[bi * 3 + 2] = v1z + cxz;
    g_tr[bi] = smf[O_TOT + 6];
  }
  if (tid < 32) {
    out[b * SD + 768 + i * 32 + tid] = smf[O_TOT + 7 + tid] * (1.f / (float)NK) + fb2[tid];
  }
}

__global__ __launch_bounds__(256) void fd_final(float* __restrict__ out)
{
  __shared__ float red[8][4];
  __shared__ float tot[4];
  const int b = blockIdx.x;
  const int tid = threadIdx.x;

  const float v0 = g_vx[(b * NPTS + tid) * 3 + 0];
  const float v1 = g_vx[(b * NPTS + tid) * 3 + 1];
  const float v2 = g_vx[(b * NPTS + tid) * 3 + 2];
  const float v3 = g_tr[b * NPTS + tid];

  float r0 = v0, r1 = v1, r2 = v2, r3 = v3;
  #pragma unroll
  for (int o = 16; o; o >>= 1) {
    r0 += __shfl_xor_sync(0xffffffffu, r0, o);
    r1 += __shfl_xor_sync(0xffffffffu, r1, o);
    r2 += __shfl_xor_sync(0xffffffffu, r2, o);
    r3 += __shfl_xor_sync(0xffffffffu, r3, o);
  }
  const int wid = tid >> 5, lane = tid & 31;
  if (lane == 0) { red[wid][0] = r0; red[wid][1] = r1; red[wid][2] = r2; red[wid][3] = r3; }
  __syncthreads();
  if (tid < 4) {
    float s = 0.f;
    #pragma unroll
    for (int w = 0; w < 8; w++) s += red[w][tid];
    tot[tid] = s;
  }
  __syncthreads();

  const float invn = 1.f / (float)NPTS;
  out[b * SD + tid * 3 + 0] = v0 - tot[0] * invn;
  out[b * SD + tid * 3 + 1] = v1 - tot[1] * invn;
  out[b * SD + tid * 3 + 2] = v2 - tot[2] * invn;
  if (tid == 0) out[NBATCH * SD + b] = tot[3] * (1.f / (float)NK);
}

extern "C" void kernel_launch(void* const* d_in, const int* in_sizes, int n_in,
                              void* d_out, int out_size)
{
  const float* state = (const float*)d_in[1];
  const float* mus   = (const float*)d_in[2];
  const float* gam   = (const float*)d_in[3];
  const float* s1W1  = (const float*)d_in[4];
  const float* s1b1  = (const float*)d_in[5];
  const float* s1W2  = (const float*)d_in[6];
  const float* s1b2  = (const float*)d_in[7];
  const float* s2W1  = (const float*)d_in[8];
  const float* s2b1  = (const float*)d_in[9];
  const float* s2W2  = (const float*)d_in[10];
  const float* s2b2  = (const float*)d_in[11];
  const float* fW1   = (const float*)d_in[12];
  const float* fb1   = (const float*)d_in[13];
  const float* fW2   = (const float*)d_in[14];
  const float* fb2   = (const float*)d_in[15];
  float* out = (float*)d_out;

  const int smem_bytes = SMEM_FLOATS * (int)sizeof(float);
  cudaFuncSetAttribute(fd_main, cudaFuncAttributeMaxDynamicSharedMemorySize, smem_bytes);

  fd_main<<<NBATCH * NPTS, 256, smem_bytes>>>(
      state, mus, gam,
      s1W1, s1b1, s1W2, s1b2,
      s2W1, s2b1, s2W2, s2b2,
      fW1, fb1, fW2, fb2, out);
  fd_final<<<NBATCH, 256>>>(out);
}

// round 4
// speedup vs baseline: 1.0686x; 1.0686x over previous
#include <cuda_runtime.h>
#include <math.h>

#define NBATCH 8
#define NPTS   256
#define NFEAT  32
#define NRBF_  50
#define NH     128
#define NK     255          // NPTS-1
#define SD     8960         // NPTS*3 + NPTS*32

// scratch (no allocations allowed)
__device__ float g_vx[NBATCH * NPTS * 3];
__device__ float g_tr[NBATCH * NPTS];

typedef unsigned long long u64;

__device__ __forceinline__ u64 pack2(float x, float y) {
  u64 r; asm("mov.b64 %0,{%1,%2};" : "=l"(r) : "f"(x), "f"(y)); return r;
}
__device__ __forceinline__ float2 unpack2(u64 v) {
  float2 f; asm("mov.b64 {%0,%1},%2;" : "=f"(f.x), "=f"(f.y) : "l"(v)); return f;
}
__device__ __forceinline__ u64 ffma2(u64 a, u64 b, u64 c) {
  u64 d; asm("fma.rn.f32x2 %0,%1,%2,%3;" : "=l"(d) : "l"(a), "l"(b), "l"(c)); return d;
}

// ---- shared memory layout (floats) ----
#define O_W1S1 0                     // 50*128 s1_W1 rbf block
#define O_W1SM (O_W1S1 + 6400)      // mu[m]*s1_W1
#define O_W1S2 (O_W1SM + 6400)      // s2_W1 rbf block
#define O_W1SF (O_W1S2 + 6400)      // f_W1 rbf block
#define O_FW2  (O_W1SF + 6400)      // 128*32
#define O_W2S1 (O_FW2 + 4096)       // 128
#define O_W2S2 (O_W2S1 + 128)       // 128
#define O_CF1  (O_W2S2 + 128)       // 128
#define O_CF2  (O_CF1 + 128)        // 128
#define O_CFF  (O_CF2 + 128)        // 128
#define O_XS   (O_CFF + 128)        // 768 positions
#define O_FS   (O_XS + 768)         // 32 feats
#define O_SMX  (O_FS + 32)          // 32 softmax(feats)
#define O_MUS  (O_SMX + 32)         // 64 (50 used)
#define O_RED  (O_MUS + 64)         // 8*40 reduction scratch
#define O_TOT  (O_RED + 320)        // 40 totals
#define SMEM_FLOATS (O_TOT + 40)

// per-hidden-lane epilogue (vf accumulate via FFMA2)
#define EPILOGUE(A1, AM, A2, AF, C1, C2, CF, W21, W22, HIDX) do {            \
    float z1 = (A1) + (C1);                                                  \
    float sg1 = __fdividef(1.f, 1.f + __expf(-z1));                          \
    s1a = fmaf(z1 * sg1, (W21), s1a);                                        \
    float sp = sg1 * (1.f + z1 * (1.f - sg1));                               \
    da = fmaf((W21) * sp, fmaf(dloc, (A1), -(AM)), da);                      \
    float z2 = (A2) + (C2);                                                  \
    float sg2 = __fdividef(1.f, 1.f + __expf(-z2));                          \
    s2a = fmaf(z2 * sg2, (W22), s2a);                                        \
    float zf = (AF) + (CF);                                                  \
    float sgf = __fdividef(1.f, 1.f + __expf(-zf));                          \
    float slf = zf * sgf;                                                    \
    {                                                                        \
      const u64 slf2 = pack2(slf, slf);                                      \
      const ulonglong2* fwrow =                                              \
          reinterpret_cast<const ulonglong2*>(&smf[O_FW2 + (HIDX) * 32]);    \
      _Pragma("unroll")                                                      \
      for (int q = 0; q < 8; q++) {                                          \
        const ulonglong2 wv = fwrow[q];                                      \
        vf2[2 * q + 0] = ffma2(slf2, wv.x, vf2[2 * q + 0]);                  \
        vf2[2 * q + 1] = ffma2(slf2, wv.y, vf2[2 * q + 1]);                  \
      }                                                                      \
    }                                                                        \
  } while (0)

__global__ __launch_bounds__(256, 1) void fd_main(
    const float* __restrict__ state, const float* __restrict__ mus,
    const float* __restrict__ gamma_p,
    const float* __restrict__ s1W1, const float* __restrict__ s1b1,
    const float* __restrict__ s1W2, const float* __restrict__ s1b2,
    const float* __restrict__ s2W1, const float* __restrict__ s2b1,
    const float* __restrict__ s2W2, const float* __restrict__ s2b2,
    const float* __restrict__ fW1, const float* __restrict__ fb1,
    const float* __restrict__ fW2, const float* __restrict__ fb2,
    float* __restrict__ out)
{
  extern __shared__ float smf[];
  const int tid = threadIdx.x;
  const int bi = blockIdx.x;
  const int b = bi >> 8;
  const int i = bi & 255;
  const float gam = gamma_p[0];

  // --- stage weights / inputs into smem ---
  for (int idx = tid; idx < 6400; idx += 256) {
    float w = s1W1[idx];
    smf[O_W1S1 + idx] = w;
    smf[O_W1SM + idx] = w * mus[idx >> 7];
    smf[O_W1S2 + idx] = s2W1[idx];
    smf[O_W1SF + idx] = fW1[idx];
  }
  for (int idx = tid; idx < 4096; idx += 256) smf[O_FW2 + idx] = fW2[idx];
  if (tid < 128) {
    smf[O_W2S1 + tid] = s1W2[tid];
    smf[O_W2S2 + tid] = s2W2[tid];
  }
  for (int idx = tid; idx < 768; idx += 256) smf[O_XS + idx] = state[b * SD + idx];
  if (tid < 32) smf[O_FS + tid] = state[b * SD + 768 + i * 32 + tid];
  if (tid < 64) smf[O_MUS + tid] = (tid < NRBF_) ? mus[tid] : 0.f;
  __syncthreads();

  // softmax(feats) by warp 0
  if (tid < 32) {
    float v = smf[O_FS + tid];
    float mx = v;
    #pragma unroll
    for (int o = 16; o; o >>= 1) mx = fmaxf(mx, __shfl_xor_sync(0xffffffffu, mx, o));
    float e = __expf(v - mx);
    float s = e;
    #pragma unroll
    for (int o = 16; o; o >>= 1) s += __shfl_xor_sync(0xffffffffu, s, o);
    smf[O_SMX + tid] = __fdividef(e, s);
  }
  __syncthreads();

  // per-(b,i) constant hidden contributions (feat columns + bias)
  if (tid < 128) {
    const int h = tid;
    float c1 = s1b1[h], c2 = s2b1[h], cf = fb1[h];
    #pragma unroll 4
    for (int f = 0; f < 32; f++) {
      float fv = smf[O_FS + f];
      c1 = fmaf(fv, s1W1[(50 + f) * 128 + h] + s1W1[(82 + f) * 128 + h], c1);
      c2 = fmaf(fv, s2W1[(50 + f) * 128 + h] + s2W1[(82 + f) * 128 + h], c2);
      cf = fmaf(smf[O_SMX + f], fW1[(50 + f) * 128 + h], cf);
    }
    smf[O_CF1 + h] = c1;
    smf[O_CF2 + h] = c2;
    smf[O_CFF + h] = cf;
  }
  __syncthreads();

  // --- per-neighbor compute: thread tid handles k = tid ---
  float s1rx = 0.f, s1ry = 0.f, s1rz = 0.f;
  float s2rx = 0.f, s2ry = 0.f, s2rz = 0.f;
  float trc = 0.f;
  u64 vf2[16];
  #pragma unroll
  for (int f = 0; f < 16; f++) vf2[f] = 0ull;

  if (tid < NK) {
    const int k = tid;
    const int j = (k < i) ? k : k + 1;
    const float rx = smf[O_XS + i * 3 + 0] - smf[O_XS + j * 3 + 0];
    const float ry = smf[O_XS + i * 3 + 1] - smf[O_XS + j * 3 + 1];
    const float rz = smf[O_XS + i * 3 + 2] - smf[O_XS + j * 3 + 2];
    const float rr2 = rx * rx + ry * ry + rz * rz;
    const float dloc = sqrtf(rr2 + 1e-6f);

    float rbf[NRBF_];
    #pragma unroll
    for (int m = 0; m < NRBF_; m++) {
      float dm = dloc - smf[O_MUS + m];
      rbf[m] = __expf(-gam * dm * dm);
    }

    float s1a = 0.f, s2a = 0.f, da = 0.f;

    #pragma unroll 1
    for (int hb = 0; hb < 128; hb += 4) {
      u64 A1a = 0ull, A1b = 0ull;
      u64 AMa = 0ull, AMb = 0ull;
      u64 A2a = 0ull, A2b = 0ull;
      u64 AFa = 0ull, AFb = 0ull;
      #pragma unroll
      for (int m = 0; m < NRBF_; m++) {
        const u64 rv2 = pack2(rbf[m], rbf[m]);
        const ulonglong2 w1 =
            *reinterpret_cast<const ulonglong2*>(&smf[O_W1S1 + m * 128 + hb]);
        A1a = ffma2(rv2, w1.x, A1a);
        A1b = ffma2(rv2, w1.y, A1b);
        const ulonglong2 wm =
            *reinterpret_cast<const ulonglong2*>(&smf[O_W1SM + m * 128 + hb]);
        AMa = ffma2(rv2, wm.x, AMa);
        AMb = ffma2(rv2, wm.y, AMb);
        const ulonglong2 w2 =
            *reinterpret_cast<const ulonglong2*>(&smf[O_W1S2 + m * 128 + hb]);
        A2a = ffma2(rv2, w2.x, A2a);
        A2b = ffma2(rv2, w2.y, A2b);
        const ulonglong2 wf =
            *reinterpret_cast<const ulonglong2*>(&smf[O_W1SF + m * 128 + hb]);
        AFa = ffma2(rv2, wf.x, AFa);
        AFb = ffma2(rv2, wf.y, AFb);
      }
      const float2 a1lo = unpack2(A1a), a1hi = unpack2(A1b);
      const float2 amlo = unpack2(AMa), amhi = unpack2(AMb);
      const float2 a2lo = unpack2(A2a), a2hi = unpack2(A2b);
      const float2 aflo = unpack2(AFa), afhi = unpack2(AFb);
      const float4 c1v = *reinterpret_cast<const float4*>(&smf[O_CF1 + hb]);
      const float4 c2v = *reinterpret_cast<const float4*>(&smf[O_CF2 + hb]);
      const float4 cfv = *reinterpret_cast<const float4*>(&smf[O_CFF + hb]);
      const float4 w21 = *reinterpret_cast<const float4*>(&smf[O_W2S1 + hb]);
      const float4 w22 = *reinterpret_cast<const float4*>(&smf[O_W2S2 + hb]);
      EPILOGUE(a1lo.x, amlo.x, a2lo.x, aflo.x, c1v.x, c2v.x, cfv.x, w21.x, w22.x, hb + 0);
      EPILOGUE(a1lo.y, amlo.y, a2lo.y, aflo.y, c1v.y, c2v.y, cfv.y, w21.y, w22.y, hb + 1);
      EPILOGUE(a1hi.x, amhi.x, a2hi.x, afhi.x, c1v.z, c2v.z, cfv.z, w21.z, w22.z, hb + 2);
      EPILOGUE(a1hi.y, amhi.y, a2hi.y, afhi.y, c1v.w, c2v.w, cfv.w, w21.w, w22.w, hb + 3);
    }

    s1a += s1b2[0];
    s2a += s2b2[0];
    // gd = ds1/dd * r2d ;  ds1/dd = -2*gamma * sum_h W2[h]*silu'(z1_h)*(d*a1_h - am_h)
    const float gd = -2.f * gam * da * __fdividef(rr2, dloc);
    s1rx = s1a * rx; s1ry = s1a * ry; s1rz = s1a * rz;
    s2rx = s2a * rx; s2ry = s2a * ry; s2rz = s2a * rz;
    trc = gd + 3.f * s1a;
  }

  // --- block reduction over neighbors (39 values) ---
  float vals[39];
  vals[0] = s1rx; vals[1] = s1ry; vals[2] = s1rz;
  vals[3] = s2rx; vals[4] = s2ry; vals[5] = s2rz;
  vals[6] = trc;
  #pragma unroll
  for (int f = 0; f < 16; f++) {
    const float2 v = unpack2(vf2[f]);
    vals[7 + 2 * f + 0] = v.x;
    vals[7 + 2 * f + 1] = v.y;
  }

  #pragma unroll
  for (int c = 0; c < 39; c++) {
    float v = vals[c];
    #pragma unroll
    for (int o = 16; o; o >>= 1) v += __shfl_xor_sync(0xffffffffu, v, o);
    vals[c] = v;
  }
  const int wid = tid >> 5, lane = tid & 31;
  if (lane == 0) {
    #pragma unroll
    for (int c = 0; c < 39; c++) smf[O_RED + wid * 40 + c] = vals[c];
  }
  __syncthreads();
  if (tid < 39) {
    float s = 0.f;
    #pragma unroll
    for (int w = 0; w < 8; w++) s += smf[O_RED + w * 40 + tid];
    smf[O_TOT + tid] = s;
  }
  __syncthreads();

  if (tid == 0) {
    const float inv = 1.f / (float)NK;
    const float v1x = smf[O_TOT + 0] * inv;
    const float v1y = smf[O_TOT + 1] * inv;
    const float v1z = smf[O_TOT + 2] * inv;
    const float m2x = smf[O_TOT + 3] * inv;
    const float m2y = smf[O_TOT + 4] * inv;
    const float m2z = smf[O_TOT + 5] * inv;
    // mean_k( s2 * (r x v1) ) = (mean_k s2*r) x v1
    const float cxx = m2y * v1z - m2z * v1y;
    const float cxy = m2z * v1x - m2x * v1z;
    const float cxz = m2x * v1y - m2y * v1x;
    g_vx[bi * 3 + 0] = v1x + cxx;
    g_vx[bi * 3 + 1] = v1y + cxy;
    g_vx[bi * 3 + 2] = v1z + cxz;
    g_tr[bi] = smf[O_TOT + 6];
  }
  if (tid < 32) {
    out[b * SD + 768 + i * 32 + tid] = smf[O_TOT + 7 + tid] * (1.f / (float)NK) + fb2[tid];
  }
}

__global__ __launch_bounds__(256) void fd_final(float* __restrict__ out)
{
  __shared__ float red[8][4];
  __shared__ float tot[4];
  const int b = blockIdx.x;
  const int tid = threadIdx.x;

  const float v0 = g_vx[(b * NPTS + tid) * 3 + 0];
  const float v1 = g_vx[(b * NPTS + tid) * 3 + 1];
  const float v2 = g_vx[(b * NPTS + tid) * 3 + 2];
  const float v3 = g_tr[b * NPTS + tid];

  float r0 = v0, r1 = v1, r2 = v2, r3 = v3;
  #pragma unroll
  for (int o = 16; o; o >>= 1) {
    r0 += __shfl_xor_sync(0xffffffffu, r0, o);
    r1 += __shfl_xor_sync(0xffffffffu, r1, o);
    r2 += __shfl_xor_sync(0xffffffffu, r2, o);
    r3 += __shfl_xor_sync(0xffffffffu, r3, o);
  }
  const int wid = tid >> 5, lane = tid & 31;
  if (lane == 0) { red[wid][0] = r0; red[wid][1] = r1; red[wid][2] = r2; red[wid][3] = r3; }
  __syncthreads();
  if (tid < 4) {
    float s = 0.f;
    #pragma unroll
    for (int w = 0; w < 8; w++) s += red[w][tid];
    tot[tid] = s;
  }
  __syncthreads();

  const float invn = 1.f / (float)NPTS;
  out[b * SD + tid * 3 + 0] = v0 - tot[0] * invn;
  out[b * SD + tid * 3 + 1] = v1 - tot[1] * invn;
  out[b * SD + tid * 3 + 2] = v2 - tot[2] * invn;
  if (tid == 0) out[NBATCH * SD + b] = tot[3] * (1.f / (float)NK);
}

extern "C" void kernel_launch(void* const* d_in, const int* in_sizes, int n_in,
                              void* d_out, int out_size)
{
  const float* state = (const float*)d_in[1];
  const float* mus   = (const float*)d_in[2];
  const float* gam   = (const float*)d_in[3];
  const float* s1W1  = (const float*)d_in[4];
  const float* s1b1  = (const float*)d_in[5];
  const float* s1W2  = (const float*)d_in[6];
  const float* s1b2  = (const float*)d_in[7];
  const float* s2W1  = (const float*)d_in[8];
  const float* s2b1  = (const float*)d_in[9];
  const float* s2W2  = (const float*)d_in[10];
  const float* s2b2  = (const float*)d_in[11];
  const float* fW1   = (const float*)d_in[12];
  const float* fb1   = (const float*)d_in[13];
  const float* fW2   = (const float*)d_in[14];
  const float* fb2   = (const float*)d_in[15];
  float* out = (float*)d_out;

  const int smem_bytes = SMEM_FLOATS * (int)sizeof(float);
  cudaFuncSetAttribute(fd_main, cudaFuncAttributeMaxDynamicSharedMemorySize, smem_bytes);

  fd_main<<<NBATCH * NPTS, 256, smem_bytes>>>(
      state, mus, gam,
      s1W1, s1b1, s1W2, s1b2,
      s2W1, s2b1, s2W2, s2b2,
      fW1, fb1, fW2, fb2, out);
  fd_final<<<NBATCH, 256>>>(out);
}

// round 5
// speedup vs baseline: 1.3837x; 1.2949x over previous
#include <cuda_runtime.h>
#include <math.h>

#define NBATCH 8
#define NPTS   256
#define NFEAT  32
#define NRBF_  50
#define NH     128
#define NK     255          // NPTS-1
#define SD     8960         // NPTS*3 + NPTS*32

// scratch (no allocations allowed)
__device__ float g_vx[NBATCH * NPTS * 3];
__device__ float g_tr[NBATCH * NPTS];

typedef unsigned long long u64;

__device__ __forceinline__ u64 pack2(float x, float y) {
  u64 r; asm("mov.b64 %0,{%1,%2};" : "=l"(r) : "f"(x), "f"(y)); return r;
}
__device__ __forceinline__ float2 unpack2(u64 v) {
  float2 f; asm("mov.b64 {%0,%1},%2;" : "=f"(f.x), "=f"(f.y) : "l"(v)); return f;
}
__device__ __forceinline__ u64 ffma2(u64 a, u64 b, u64 c) {
  u64 d; asm("fma.rn.f32x2 %0,%1,%2,%3;" : "=l"(d) : "l"(a), "l"(b), "l"(c)); return d;
}

// ---- shared memory layout (floats) ----
#define O_W1   0                    // 50*128 s1_W1 rbf block
#define O_W2   (O_W1 + 6400)        // s2_W1 rbf block
#define O_WF   (O_W2 + 6400)        // f_W1 rbf block
#define O_V21  (O_WF + 6400)        // 128 s1_W2
#define O_V22  (O_V21 + 128)        // 128 s2_W2
#define O_CF1  (O_V22 + 128)        // 128
#define O_CF2  (O_CF1 + 128)        // 128
#define O_CFF  (O_CF2 + 128)        // 128
#define O_XS   (O_CFF + 128)        // 768 positions
#define O_FS   (O_XS + 768)         // 32 feats
#define O_SMX  (O_FS + 32)          // 32 softmax(feats)
#define O_MUS  (O_SMX + 32)         // 64 (50 used)
#define O_HS   (O_MUS + 64)         // 8*128 per-warp silu(zf) sums
#define O_HT   (O_HS + 1024)        // 128 totals
#define O_RED  (O_HT + 128)         // 8*8 reduction scratch
#define O_TOT  (O_RED + 64)         // 8 totals
#define SMEM_FLOATS (O_TOT + 8)

// per-hidden-lane epilogue: s1/s2/trace accum + warp-reduced silu(zf) sum
#define EPILOGUE(A1, DA, A2, AF, C1, C2, CF, W21, W22, HIDX) do {            \
    float z1 = (A1) + (C1);                                                  \
    float sg1 = __fdividef(1.f, 1.f + __expf(-z1));                          \
    s1a = fmaf(z1 * sg1, (W21), s1a);                                        \
    float sp = sg1 * (1.f + z1 * (1.f - sg1));                               \
    da = fmaf((W21) * sp, (DA), da);                                         \
    float z2 = (A2) + (C2);                                                  \
    float sg2 = __fdividef(1.f, 1.f + __expf(-z2));                          \
    s2a = fmaf(z2 * sg2, (W22), s2a);                                        \
    float zf = (AF) + (CF);                                                  \
    float sgf = __fdividef(1.f, 1.f + __expf(-zf));                          \
    float slf = zf * sgf * act;                                              \
    _Pragma("unroll")                                                        \
    for (int o = 16; o; o >>= 1) slf += __shfl_xor_sync(0xffffffffu, slf, o);\
    if (lane == 0) smf[O_HS + wid * 128 + (HIDX)] += slf;                    \
  } while (0)

__global__ __launch_bounds__(256, 1) void fd_main(
    const float* __restrict__ state, const float* __restrict__ mus,
    const float* __restrict__ gamma_p,
    const float* __restrict__ s1W1, const float* __restrict__ s1b1,
    const float* __restrict__ s1W2, const float* __restrict__ s1b2,
    const float* __restrict__ s2W1, const float* __restrict__ s2b1,
    const float* __restrict__ s2W2, const float* __restrict__ s2b2,
    const float* __restrict__ fW1, const float* __restrict__ fb1,
    const float* __restrict__ fW2, const float* __restrict__ fb2,
    float* __restrict__ out)
{
  extern __shared__ float smf[];
  const int tid = threadIdx.x;
  const int wid = tid >> 5, lane = tid & 31;
  const int bi = blockIdx.x;
  const int b = bi >> 8;
  const int i = bi & 255;
  const float gam = gamma_p[0];

  // --- stage weights / inputs into smem ---
  for (int idx = tid; idx < 6400; idx += 256) {
    smf[O_W1 + idx] = s1W1[idx];
    smf[O_W2 + idx] = s2W1[idx];
    smf[O_WF + idx] = fW1[idx];
  }
  if (tid < 128) {
    smf[O_V21 + tid] = s1W2[tid];
    smf[O_V22 + tid] = s2W2[tid];
  }
  for (int idx = tid; idx < 1024; idx += 256) smf[O_HS + idx] = 0.f;
  for (int idx = tid; idx < 768; idx += 256) smf[O_XS + idx] = state[b * SD + idx];
  if (tid < 32) smf[O_FS + tid] = state[b * SD + 768 + i * 32 + tid];
  if (tid < 64) smf[O_MUS + tid] = (tid < NRBF_) ? mus[tid] : 0.f;
  __syncthreads();

  // softmax(feats) by warp 0
  if (tid < 32) {
    float v = smf[O_FS + tid];
    float mx = v;
    #pragma unroll
    for (int o = 16; o; o >>= 1) mx = fmaxf(mx, __shfl_xor_sync(0xffffffffu, mx, o));
    float e = __expf(v - mx);
    float s = e;
    #pragma unroll
    for (int o = 16; o; o >>= 1) s += __shfl_xor_sync(0xffffffffu, s, o);
    smf[O_SMX + tid] = __fdividef(e, s);
  }
  __syncthreads();

  // per-(b,i) constant hidden contributions (feat columns + bias)
  if (tid < 128) {
    const int h = tid;
    float c1 = s1b1[h], c2 = s2b1[h], cf = fb1[h];
    #pragma unroll 4
    for (int f = 0; f < 32; f++) {
      float fv = smf[O_FS + f];
      c1 = fmaf(fv, s1W1[(50 + f) * 128 + h] + s1W1[(82 + f) * 128 + h], c1);
      c2 = fmaf(fv, s2W1[(50 + f) * 128 + h] + s2W1[(82 + f) * 128 + h], c2);
      cf = fmaf(smf[O_SMX + f], fW1[(50 + f) * 128 + h], cf);
    }
    smf[O_CF1 + h] = c1;
    smf[O_CF2 + h] = c2;
    smf[O_CFF + h] = cf;
  }
  __syncthreads();

  // --- per-neighbor compute: thread tid handles k = tid (255 real, tid=255
  //     duplicates k=254 with act=0 so warp-collective shfls stay uniform) ---
  const float act = (tid < NK) ? 1.f : 0.f;
  const int k = (tid < NK) ? tid : NK - 1;
  const int j = (k < i) ? k : k + 1;
  const float rx = smf[O_XS + i * 3 + 0] - smf[O_XS + j * 3 + 0];
  const float ry = smf[O_XS + i * 3 + 1] - smf[O_XS + j * 3 + 1];
  const float rz = smf[O_XS + i * 3 + 2] - smf[O_XS + j * 3 + 2];
  const float rr2 = rx * rx + ry * ry + rz * rz;
  const float dloc = sqrtf(rr2 + 1e-6f);

  float rbf[NRBF_], rbfd[NRBF_];
  #pragma unroll
  for (int m = 0; m < NRBF_; m++) {
    float dm = dloc - smf[O_MUS + m];
    float rv = __expf(-gam * dm * dm);
    rbf[m] = rv;
    rbfd[m] = rv * dm;     // rbf*(d-mu): drives d(z1)/dd via the SAME W1
  }

  float s1a = 0.f, s2a = 0.f, da = 0.f;

  #pragma unroll 1
  for (int hb = 0; hb < 128; hb += 4) {
    u64 A1a = 0ull, A1b = 0ull;
    u64 DAa = 0ull, DAb = 0ull;
    u64 A2a = 0ull, A2b = 0ull;
    u64 AFa = 0ull, AFb = 0ull;
    #pragma unroll
    for (int m = 0; m < NRBF_; m++) {
      const u64 rv2 = pack2(rbf[m], rbf[m]);
      const u64 rd2 = pack2(rbfd[m], rbfd[m]);
      const ulonglong2 w1 =
          *reinterpret_cast<const ulonglong2*>(&smf[O_W1 + m * 128 + hb]);
      A1a = ffma2(rv2, w1.x, A1a);
      A1b = ffma2(rv2, w1.y, A1b);
      DAa = ffma2(rd2, w1.x, DAa);
      DAb = ffma2(rd2, w1.y, DAb);
      const ulonglong2 w2 =
          *reinterpret_cast<const ulonglong2*>(&smf[O_W2 + m * 128 + hb]);
      A2a = ffma2(rv2, w2.x, A2a);
      A2b = ffma2(rv2, w2.y, A2b);
      const ulonglong2 wf =
          *reinterpret_cast<const ulonglong2*>(&smf[O_WF + m * 128 + hb]);
      AFa = ffma2(rv2, wf.x, AFa);
      AFb = ffma2(rv2, wf.y, AFb);
    }
    const float2 a1lo = unpack2(A1a), a1hi = unpack2(A1b);
    const float2 dalo = unpack2(DAa), dahi = unpack2(DAb);
    const float2 a2lo = unpack2(A2a), a2hi = unpack2(A2b);
    const float2 aflo = unpack2(AFa), afhi = unpack2(AFb);
    const float4 c1v = *reinterpret_cast<const float4*>(&smf[O_CF1 + hb]);
    const float4 c2v = *reinterpret_cast<const float4*>(&smf[O_CF2 + hb]);
    const float4 cfv = *reinterpret_cast<const float4*>(&smf[O_CFF + hb]);
    const float4 w21 = *reinterpret_cast<const float4*>(&smf[O_V21 + hb]);
    const float4 w22 = *reinterpret_cast<const float4*>(&smf[O_V22 + hb]);
    EPILOGUE(a1lo.x, dalo.x, a2lo.x, aflo.x, c1v.x, c2v.x, cfv.x, w21.x, w22.x, hb + 0);
    EPILOGUE(a1lo.y, dalo.y, a2lo.y, aflo.y, c1v.y, c2v.y, cfv.y, w21.y, w22.y, hb + 1);
    EPILOGUE(a1hi.x, dahi.x, a2hi.x, afhi.x, c1v.z, c2v.z, cfv.z, w21.z, w22.z, hb + 2);
    EPILOGUE(a1hi.y, dahi.y, a2hi.y, afhi.y, c1v.w, c2v.w, cfv.w, w21.w, w22.w, hb + 3);
  }

  // --- per-thread scalar outputs (only for real neighbors) ---
  float vals[7];
  #pragma unroll
  for (int c = 0; c < 7; c++) vals[c] = 0.f;
  if (tid < NK) {
    const float s1v = s1a + s1b2[0];
    const float s2v = s2a + s2b2[0];
    // gd = ds1/dd * r2d ;  ds1/dd = -2*gamma * sum_h W2[h]*silu'(z1_h)*DA1_h
    const float gd = -2.f * gam * da * __fdividef(rr2, dloc);
    vals[0] = s1v * rx; vals[1] = s1v * ry; vals[2] = s1v * rz;
    vals[3] = s2v * rx; vals[4] = s2v * ry; vals[5] = s2v * rz;
    vals[6] = gd + 3.f * s1v;
  }

  // --- block reduction over neighbors (7 values) ---
  #pragma unroll
  for (int c = 0; c < 7; c++) {
    float v = vals[c];
    #pragma unroll
    for (int o = 16; o; o >>= 1) v += __shfl_xor_sync(0xffffffffu, v, o);
    vals[c] = v;
  }
  if (lane == 0) {
    #pragma unroll
    for (int c = 0; c < 7; c++) smf[O_RED + wid * 8 + c] = vals[c];
  }
  __syncthreads();
  if (tid < 7) {
    float s = 0.f;
    #pragma unroll
    for (int w = 0; w < 8; w++) s += smf[O_RED + w * 8 + tid];
    smf[O_TOT + tid] = s;
  }
  // cross-warp reduce of per-warp silu(zf) hidden sums
  if (tid < 128) {
    float s = 0.f;
    #pragma unroll
    for (int w = 0; w < 8; w++) s += smf[O_HS + w * 128 + tid];
    smf[O_HT + tid] = s;
  }
  __syncthreads();

  if (tid == 0) {
    const float inv = 1.f / (float)NK;
    const float v1x = smf[O_TOT + 0] * inv;
    const float v1y = smf[O_TOT + 1] * inv;
    const float v1z = smf[O_TOT + 2] * inv;
    const float m2x = smf[O_TOT + 3] * inv;
    const float m2y = smf[O_TOT + 4] * inv;
    const float m2z = smf[O_TOT + 5] * inv;
    // mean_k( s2 * (r x v1) ) = (mean_k s2*r) x v1
    const float cxx = m2y * v1z - m2z * v1y;
    const float cxy = m2z * v1x - m2x * v1z;
    const float cxz = m2x * v1y - m2y * v1x;
    g_vx[bi * 3 + 0] = v1x + cxx;
    g_vx[bi * 3 + 1] = v1y + cxy;
    g_vx[bi * 3 + 2] = v1z + cxz;
    g_tr[bi] = smf[O_TOT + 6];
  }
  // v_feats = (mean_k silu(zf)) @ fW2 + fb2   (fW2 is linear -> commutes with mean)
  if (tid < 32) {
    float acc = 0.f;
    #pragma unroll 8
    for (int h = 0; h < 128; h++) acc = fmaf(smf[O_HT + h], fW2[h * 32 + tid], acc);
    out[b * SD + 768 + i * 32 + tid] = acc * (1.f / (float)NK) + fb2[tid];
  }
}

__global__ __launch_bounds__(256) void fd_final(float* __restrict__ out)
{
  __shared__ float red[8][4];
  __shared__ float tot[4];
  const int b = blockIdx.x;
  const int tid = threadIdx.x;

  const float v0 = g_vx[(b * NPTS + tid) * 3 + 0];
  const float v1 = g_vx[(b * NPTS + tid) * 3 + 1];
  const float v2 = g_vx[(b * NPTS + tid) * 3 + 2];
  const float v3 = g_tr[b * NPTS + tid];

  float r0 = v0, r1 = v1, r2 = v2, r3 = v3;
  #pragma unroll
  for (int o = 16; o; o >>= 1) {
    r0 += __shfl_xor_sync(0xffffffffu, r0, o);
    r1 += __shfl_xor_sync(0xffffffffu, r1, o);
    r2 += __shfl_xor_sync(0xffffffffu, r2, o);
    r3 += __shfl_xor_sync(0xffffffffu, r3, o);
  }
  const int wid = tid >> 5, lane = tid & 31;
  if (lane == 0) { red[wid][0] = r0; red[wid][1] = r1; red[wid][2] = r2; red[wid][3] = r3; }
  __syncthreads();
  if (tid < 4) {
    float s = 0.f;
    #pragma unroll
    for (int w = 0; w < 8; w++) s += red[w][tid];
    tot[tid] = s;
  }
  __syncthreads();

  const float invn = 1.f / (float)NPTS;
  out[b * SD + tid * 3 + 0] = v0 - tot[0] * invn;
  out[b * SD + tid * 3 + 1] = v1 - tot[1] * invn;
  out[b * SD + tid * 3 + 2] = v2 - tot[2] * invn;
  if (tid == 0) out[NBATCH * SD + b] = tot[3] * (1.f / (float)NK);
}

extern "C" void kernel_launch(void* const* d_in, const int* in_sizes, int n_in,
                              void* d_out, int out_size)
{
  const float* state = (const float*)d_in[1];
  const float* mus   = (const float*)d_in[2];
  const float* gam   = (const float*)d_in[3];
  const float* s1W1  = (const float*)d_in[4];
  const float* s1b1  = (const float*)d_in[5];
  const float* s1W2  = (const float*)d_in[6];
  const float* s1b2  = (const float*)d_in[7];
  const float* s2W1  = (const float*)d_in[8];
  const float* s2b1  = (const float*)d_in[9];
  const float* s2W2  = (const float*)d_in[10];
  const float* s2b2  = (const float*)d_in[11];
  const float* fW1   = (const float*)d_in[12];
  const float* fb1   = (const float*)d_in[13];
  const float* fW2   = (const float*)d_in[14];
  const float* fb2   = (const float*)d_in[15];
  float* out = (float*)d_out;

  const int smem_bytes = SMEM_FLOATS * (int)sizeof(float);
  cudaFuncSetAttribute(fd_main, cudaFuncAttributeMaxDynamicSharedMemorySize, smem_bytes);

  fd_main<<<NBATCH * NPTS, 256, smem_bytes>>>(
      state, mus, gam,
      s1W1, s1b1, s1W2, s1b2,
      s2W1, s2b1, s2W2, s2b2,
      fW1, fb1, fW2, fb2, out);
  fd_final<<<NBATCH, 256>>>(out);
}

// round 6
// speedup vs baseline: 1.8147x; 1.3115x over previous
#include <cuda_runtime.h>
#include <math.h>

#define NBATCH 8
#define NPTS   256
#define NFEAT  32
#define NRBF_  50
#define NH     128
#define NK     255          // NPTS-1
#define SD     8960         // NPTS*3 + NPTS*32

// scratch (no allocations allowed)
__device__ float g_vx[NBATCH * NPTS * 3];
__device__ float g_tr[NBATCH * NPTS];

typedef unsigned long long u64;

__device__ __forceinline__ u64 pack2(float x, float y) {
  u64 r; asm("mov.b64 %0,{%1,%2};" : "=l"(r) : "f"(x), "f"(y)); return r;
}
__device__ __forceinline__ float2 unpack2(u64 v) {
  float2 f; asm("mov.b64 {%0,%1},%2;" : "=f"(f.x), "=f"(f.y) : "l"(v)); return f;
}
__device__ __forceinline__ u64 ffma2(u64 a, u64 b, u64 c) {
  u64 d; asm("fma.rn.f32x2 %0,%1,%2,%3;" : "=l"(d) : "l"(a), "l"(b), "l"(c)); return d;
}

// ---- shared memory layout (floats) ----
#define O_W1   0                    // 50*128 s1_W1 rbf block
#define O_WM   (O_W1 + 6400)        // mu[m]*s1_W1 (for d(z1)/dd = d*A1 - AM)
#define O_W2   (O_WM + 6400)        // s2_W1 rbf block
#define O_WF   (O_W2 + 6400)        // f_W1 rbf block
#define O_V21  (O_WF + 6400)        // 128 s1_W2
#define O_V22  (O_V21 + 128)        // 128 s2_W2
#define O_CF1  (O_V22 + 128)        // 128
#define O_CF2  (O_CF1 + 128)        // 128
#define O_CFF  (O_CF2 + 128)        // 128
#define O_XS   (O_CFF + 128)        // 768 positions
#define O_FS   (O_XS + 768)         // 32 feats
#define O_SMX  (O_FS + 32)          // 32 softmax(feats)
#define O_MUS  (O_SMX + 32)         // 64 (50 used)
#define O_HS   (O_MUS + 64)         // 4*128 per-warp silu(zf) sums
#define O_HT   (O_HS + 512)         // 128 totals
#define O_RED  (O_HT + 128)         // 4*8 reduction scratch
#define O_TOT  (O_RED + 32)         // 8 totals
#define SMEM_FLOATS (O_TOT + 8)     // 27816 floats = 111264 B

// per-hidden-lane epilogue for BOTH neighbors
#define EPI(A11, AM1, A21, AF1, A12, AM2, A22, AF2, C1, C2, CF, W21, W22, HIDX) do { \
    float z1a = (A11) + (C1);                                                 \
    float sga = __fdividef(1.f, 1.f + __expf(-z1a));                          \
    s1a1 = fmaf(z1a * sga, (W21), s1a1);                                      \
    float spa = sga * (1.f + z1a * (1.f - sga));                              \
    da1 = fmaf((W21) * spa, fmaf(d1, (A11), -(AM1)), da1);                    \
    float z1b = (A12) + (C1);                                                 \
    float sgb = __fdividef(1.f, 1.f + __expf(-z1b));                          \
    s1a2 = fmaf(z1b * sgb, (W21), s1a2);                                      \
    float spb = sgb * (1.f + z1b * (1.f - sgb));                              \
    da2 = fmaf((W21) * spb, fmaf(d2, (A12), -(AM2)), da2);                    \
    float z2a = (A21) + (C2);                                                 \
    float g2a = __fdividef(1.f, 1.f + __expf(-z2a));                          \
    s2a1 = fmaf(z2a * g2a, (W22), s2a1);                                      \
    float z2b = (A22) + (C2);                                                 \
    float g2b = __fdividef(1.f, 1.f + __expf(-z2b));                          \
    s2a2 = fmaf(z2b * g2b, (W22), s2a2);                                      \
    float zfa = (AF1) + (CF);                                                 \
    float gfa = __fdividef(1.f, 1.f + __expf(-zfa));                          \
    float zfb = (AF2) + (CF);                                                 \
    float gfb = __fdividef(1.f, 1.f + __expf(-zfb));                          \
    float slf = fmaf(zfb * gfb, act2, zfa * gfa);                             \
    _Pragma("unroll")                                                         \
    for (int o = 16; o; o >>= 1) slf += __shfl_xor_sync(0xffffffffu, slf, o); \
    if (lane == 0) smf[O_HS + wid * 128 + (HIDX)] += slf;                     \
  } while (0)

__global__ __launch_bounds__(128, 2) void fd_main(
    const float* __restrict__ state, const float* __restrict__ mus,
    const float* __restrict__ gamma_p,
    const float* __restrict__ s1W1, const float* __restrict__ s1b1,
    const float* __restrict__ s1W2, const float* __restrict__ s1b2,
    const float* __restrict__ s2W1, const float* __restrict__ s2b1,
    const float* __restrict__ s2W2, const float* __restrict__ s2b2,
    const float* __restrict__ fW1, const float* __restrict__ fb1,
    const float* __restrict__ fW2, const float* __restrict__ fb2,
    float* __restrict__ out)
{
  extern __shared__ float smf[];
  const int tid = threadIdx.x;
  const int wid = tid >> 5, lane = tid & 31;
  const int bi = blockIdx.x;
  const int b = bi >> 8;
  const int i = bi & 255;
  const float gam = gamma_p[0];

  // --- stage weights / inputs into smem ---
  for (int idx = tid; idx < 6400; idx += 128) {
    float w = s1W1[idx];
    smf[O_W1 + idx] = w;
    smf[O_WM + idx] = w * mus[idx >> 7];
    smf[O_W2 + idx] = s2W1[idx];
    smf[O_WF + idx] = fW1[idx];
  }
  smf[O_V21 + tid] = s1W2[tid];
  smf[O_V22 + tid] = s2W2[tid];
  for (int idx = tid; idx < 512; idx += 128) smf[O_HS + idx] = 0.f;
  for (int idx = tid; idx < 768; idx += 128) smf[O_XS + idx] = state[b * SD + idx];
  if (tid < 32) smf[O_FS + tid] = state[b * SD + 768 + i * 32 + tid];
  if (tid < 64) smf[O_MUS + tid] = (tid < NRBF_) ? mus[tid] : 0.f;
  __syncthreads();

  // softmax(feats) by warp 0
  if (tid < 32) {
    float v = smf[O_FS + tid];
    float mx = v;
    #pragma unroll
    for (int o = 16; o; o >>= 1) mx = fmaxf(mx, __shfl_xor_sync(0xffffffffu, mx, o));
    float e = __expf(v - mx);
    float s = e;
    #pragma unroll
    for (int o = 16; o; o >>= 1) s += __shfl_xor_sync(0xffffffffu, s, o);
    smf[O_SMX + tid] = __fdividef(e, s);
  }
  __syncthreads();

  // per-(b,i) constant hidden contributions (feat columns + bias), one lane per h
  {
    const int h = tid;
    float c1 = s1b1[h], c2 = s2b1[h], cf = fb1[h];
    #pragma unroll 4
    for (int f = 0; f < 32; f++) {
      float fv = smf[O_FS + f];
      c1 = fmaf(fv, s1W1[(50 + f) * 128 + h] + s1W1[(82 + f) * 128 + h], c1);
      c2 = fmaf(fv, s2W1[(50 + f) * 128 + h] + s2W1[(82 + f) * 128 + h], c2);
      cf = fmaf(smf[O_SMX + f], fW1[(50 + f) * 128 + h], cf);
    }
    smf[O_CF1 + h] = c1;
    smf[O_CF2 + h] = c2;
    smf[O_CFF + h] = cf;
  }
  __syncthreads();

  // --- each thread handles neighbors k1 = tid (always real) and k2 = tid+128 ---
  const int k1 = tid;
  const int k2t = tid + 128;
  const float act2 = (k2t < NK) ? 1.f : 0.f;
  const int k2 = (k2t < NK) ? k2t : NK - 1;
  const int j1 = (k1 < i) ? k1 : k1 + 1;
  const int j2 = (k2 < i) ? k2 : k2 + 1;
  const float xi0 = smf[O_XS + i * 3 + 0];
  const float xi1 = smf[O_XS + i * 3 + 1];
  const float xi2 = smf[O_XS + i * 3 + 2];
  const float rx1 = xi0 - smf[O_XS + j1 * 3 + 0];
  const float ry1 = xi1 - smf[O_XS + j1 * 3 + 1];
  const float rz1 = xi2 - smf[O_XS + j1 * 3 + 2];
  const float rx2 = xi0 - smf[O_XS + j2 * 3 + 0];
  const float ry2 = xi1 - smf[O_XS + j2 * 3 + 1];
  const float rz2 = xi2 - smf[O_XS + j2 * 3 + 2];
  const float rr1 = rx1 * rx1 + ry1 * ry1 + rz1 * rz1;
  const float rr2q = rx2 * rx2 + ry2 * ry2 + rz2 * rz2;
  const float d1 = sqrtf(rr1 + 1e-6f);
  const float d2 = sqrtf(rr2q + 1e-6f);

  float rbf1[NRBF_], rbf2[NRBF_];
  #pragma unroll
  for (int m = 0; m < NRBF_; m++) {
    float mu = smf[O_MUS + m];
    float dm1 = d1 - mu, dm2 = d2 - mu;
    rbf1[m] = __expf(-gam * dm1 * dm1);
    rbf2[m] = __expf(-gam * dm2 * dm2);
  }

  float s1a1 = 0.f, s1a2 = 0.f, s2a1 = 0.f, s2a2 = 0.f, da1 = 0.f, da2 = 0.f;

  #pragma unroll 1
  for (int hb = 0; hb < 128; hb += 4) {
    u64 A1a1 = 0ull, A1b1 = 0ull, A1a2 = 0ull, A1b2 = 0ull;
    u64 AMa1 = 0ull, AMb1 = 0ull, AMa2 = 0ull, AMb2 = 0ull;
    u64 A2a1 = 0ull, A2b1 = 0ull, A2a2 = 0ull, A2b2 = 0ull;
    u64 AFa1 = 0ull, AFb1 = 0ull, AFa2 = 0ull, AFb2 = 0ull;
    #pragma unroll
    for (int m = 0; m < NRBF_; m++) {
      const u64 rv1 = pack2(rbf1[m], rbf1[m]);
      const u64 rv2 = pack2(rbf2[m], rbf2[m]);
      const ulonglong2 w1 =
          *reinterpret_cast<const ulonglong2*>(&smf[O_W1 + m * 128 + hb]);
      A1a1 = ffma2(rv1, w1.x, A1a1);  A1b1 = ffma2(rv1, w1.y, A1b1);
      A1a2 = ffma2(rv2, w1.x, A1a2);  A1b2 = ffma2(rv2, w1.y, A1b2);
      const ulonglong2 wm =
          *reinterpret_cast<const ulonglong2*>(&smf[O_WM + m * 128 + hb]);
      AMa1 = ffma2(rv1, wm.x, AMa1);  AMb1 = ffma2(rv1, wm.y, AMb1);
      AMa2 = ffma2(rv2, wm.x, AMa2);  AMb2 = ffma2(rv2, wm.y, AMb2);
      const ulonglong2 w2 =
          *reinterpret_cast<const ulonglong2*>(&smf[O_W2 + m * 128 + hb]);
      A2a1 = ffma2(rv1, w2.x, A2a1);  A2b1 = ffma2(rv1, w2.y, A2b1);
      A2a2 = ffma2(rv2, w2.x, A2a2);  A2b2 = ffma2(rv2, w2.y, A2b2);
      const ulonglong2 wf =
          *reinterpret_cast<const ulonglong2*>(&smf[O_WF + m * 128 + hb]);
      AFa1 = ffma2(rv1, wf.x, AFa1);  AFb1 = ffma2(rv1, wf.y, AFb1);
      AFa2 = ffma2(rv2, wf.x, AFa2);  AFb2 = ffma2(rv2, wf.y, AFb2);
    }
    const float2 a1lo1 = unpack2(A1a1), a1hi1 = unpack2(A1b1);
    const float2 a1lo2 = unpack2(A1a2), a1hi2 = unpack2(A1b2);
    const float2 amlo1 = unpack2(AMa1), amhi1 = unpack2(AMb1);
    const float2 amlo2 = unpack2(AMa2), amhi2 = unpack2(AMb2);
    const float2 a2lo1 = unpack2(A2a1), a2hi1 = unpack2(A2b1);
    const float2 a2lo2 = unpack2(A2a2), a2hi2 = unpack2(A2b2);
    const float2 aflo1 = unpack2(AFa1), afhi1 = unpack2(AFb1);
    const float2 aflo2 = unpack2(AFa2), afhi2 = unpack2(AFb2);
    const float4 c1v = *reinterpret_cast<const float4*>(&smf[O_CF1 + hb]);
    const float4 c2v = *reinterpret_cast<const float4*>(&smf[O_CF2 + hb]);
    const float4 cfv = *reinterpret_cast<const float4*>(&smf[O_CFF + hb]);
    const float4 w21 = *reinterpret_cast<const float4*>(&smf[O_V21 + hb]);
    const float4 w22 = *reinterpret_cast<const float4*>(&smf[O_V22 + hb]);
    EPI(a1lo1.x, amlo1.x, a2lo1.x, aflo1.x, a1lo2.x, amlo2.x, a2lo2.x, aflo2.x,
        c1v.x, c2v.x, cfv.x, w21.x, w22.x, hb + 0);
    EPI(a1lo1.y, amlo1.y, a2lo1.y, aflo1.y, a1lo2.y, amlo2.y, a2lo2.y, aflo2.y,
        c1v.y, c2v.y, cfv.y, w21.y, w22.y, hb + 1);
    EPI(a1hi1.x, amhi1.x, a2hi1.x, afhi1.x, a1hi2.x, amhi2.x, a2hi2.x, afhi2.x,
        c1v.z, c2v.z, cfv.z, w21.z, w22.z, hb + 2);
    EPI(a1hi1.y, amhi1.y, a2hi1.y, afhi1.y, a1hi2.y, amhi2.y, a2hi2.y, afhi2.y,
        c1v.w, c2v.w, cfv.w, w21.w, w22.w, hb + 3);
  }

  // --- per-thread scalar outputs, both neighbors folded together ---
  const float b2s1 = s1b2[0], b2s2 = s2b2[0];
  const float s1v1 = s1a1 + b2s1;
  const float s2v1 = s2a1 + b2s2;
  const float gd1 = -2.f * gam * da1 * __fdividef(rr1, d1);
  const float s1v2 = (s1a2 + b2s1) * act2;
  const float s2v2 = (s2a2 + b2s2) * act2;
  const float gd2 = -2.f * gam * da2 * __fdividef(rr2q, d2) * act2;

  float vals[7];
  vals[0] = fmaf(s1v2, rx2, s1v1 * rx1);
  vals[1] = fmaf(s1v2, ry2, s1v1 * ry1);
  vals[2] = fmaf(s1v2, rz2, s1v1 * rz1);
  vals[3] = fmaf(s2v2, rx2, s2v1 * rx1);
  vals[4] = fmaf(s2v2, ry2, s2v1 * ry1);
  vals[5] = fmaf(s2v2, rz2, s2v1 * rz1);
  vals[6] = gd1 + 3.f * s1v1 + gd2 + 3.f * s1v2;

  // --- block reduction over neighbors (7 values, 4 warps) ---
  #pragma unroll
  for (int c = 0; c < 7; c++) {
    float v = vals[c];
    #pragma unroll
    for (int o = 16; o; o >>= 1) v += __shfl_xor_sync(0xffffffffu, v, o);
    vals[c] = v;
  }
  if (lane == 0) {
    #pragma unroll
    for (int c = 0; c < 7; c++) smf[O_RED + wid * 8 + c] = vals[c];
  }
  __syncthreads();
  if (tid < 7) {
    float s = 0.f;
    #pragma unroll
    for (int w = 0; w < 4; w++) s += smf[O_RED + w * 8 + tid];
    smf[O_TOT + tid] = s;
  }
  // cross-warp reduce of per-warp silu(zf) hidden sums
  {
    float s = 0.f;
    #pragma unroll
    for (int w = 0; w < 4; w++) s += smf[O_HS + w * 128 + tid];
    smf[O_HT + tid] = s;
  }
  __syncthreads();

  if (tid == 0) {
    const float inv = 1.f / (float)NK;
    const float v1x = smf[O_TOT + 0] * inv;
    const float v1y = smf[O_TOT + 1] * inv;
    const float v1z = smf[O_TOT + 2] * inv;
    const float m2x = smf[O_TOT + 3] * inv;
    const float m2y = smf[O_TOT + 4] * inv;
    const float m2z = smf[O_TOT + 5] * inv;
    // mean_k( s2 * (r x v1) ) = (mean_k s2*r) x v1
    const float cxx = m2y * v1z - m2z * v1y;
    const float cxy = m2z * v1x - m2x * v1z;
    const float cxz = m2x * v1y - m2y * v1x;
    g_vx[bi * 3 + 0] = v1x + cxx;
    g_vx[bi * 3 + 1] = v1y + cxy;
    g_vx[bi * 3 + 2] = v1z + cxz;
    g_tr[bi] = smf[O_TOT + 6];
  }
  // v_feats = (mean_k silu(zf)) @ fW2 + fb2   (fW2 linear -> commutes with mean)
  if (tid < 32) {
    float acc = 0.f;
    #pragma unroll 8
    for (int h = 0; h < 128; h++) acc = fmaf(smf[O_HT + h], fW2[h * 32 + tid], acc);
    out[b * SD + 768 + i * 32 + tid] = acc * (1.f / (float)NK) + fb2[tid];
  }
}

__global__ __launch_bounds__(256) void fd_final(float* __restrict__ out)
{
  __shared__ float red[8][4];
  __shared__ float tot[4];
  const int b = blockIdx.x;
  const int tid = threadIdx.x;

  const float v0 = g_vx[(b * NPTS + tid) * 3 + 0];
  const float v1 = g_vx[(b * NPTS + tid) * 3 + 1];
  const float v2 = g_vx[(b * NPTS + tid) * 3 + 2];
  const float v3 = g_tr[b * NPTS + tid];

  float r0 = v0, r1 = v1, r2 = v2, r3 = v3;
  #pragma unroll
  for (int o = 16; o; o >>= 1) {
    r0 += __shfl_xor_sync(0xffffffffu, r0, o);
    r1 += __shfl_xor_sync(0xffffffffu, r1, o);
    r2 += __shfl_xor_sync(0xffffffffu, r2, o);
    r3 += __shfl_xor_sync(0xffffffffu, r3, o);
  }
  const int wid = tid >> 5, lane = tid & 31;
  if (lane == 0) { red[wid][0] = r0; red[wid][1] = r1; red[wid][2] = r2; red[wid][3] = r3; }
  __syncthreads();
  if (tid < 4) {
    float s = 0.f;
    #pragma unroll
    for (int w = 0; w < 8; w++) s += red[w][tid];
    tot[tid] = s;
  }
  __syncthreads();

  const float invn = 1.f / (float)NPTS;
  out[b * SD + tid * 3 + 0] = v0 - tot[0] * invn;
  out[b * SD + tid * 3 + 1] = v1 - tot[1] * invn;
  out[b * SD + tid * 3 + 2] = v2 - tot[2] * invn;
  if (tid == 0) out[NBATCH * SD + b] = tot[3] * (1.f / (float)NK);
}

extern "C" void kernel_launch(void* const* d_in, const int* in_sizes, int n_in,
                              void* d_out, int out_size)
{
  const float* state = (const float*)d_in[1];
  const float* mus   = (const float*)d_in[2];
  const float* gam   = (const float*)d_in[3];
  const float* s1W1  = (const float*)d_in[4];
  const float* s1b1  = (const float*)d_in[5];
  const float* s1W2  = (const float*)d_in[6];
  const float* s1b2  = (const float*)d_in[7];
  const float* s2W1  = (const float*)d_in[8];
  const float* s2b1  = (const float*)d_in[9];
  const float* s2W2  = (const float*)d_in[10];
  const float* s2b2  = (const float*)d_in[11];
  const float* fW1   = (const float*)d_in[12];
  const float* fb1   = (const float*)d_in[13];
  const float* fW2   = (const float*)d_in[14];
  const float* fb2   = (const float*)d_in[15];
  float* out = (float*)d_out;

  const int smem_bytes = SMEM_FLOATS * (int)sizeof(float);
  cudaFuncSetAttribute(fd_main, cudaFuncAttributeMaxDynamicSharedMemorySize, smem_bytes);

  fd_main<<<NBATCH * NPTS, 128, smem_bytes>>>(
      state, mus, gam,
      s1W1, s1b1, s1W2, s1b2,
      s2W1, s2b1, s2W2, s2b2,
      fW1, fb1, fW2, fb2, out);
  fd_final<<<NBATCH, 256>>>(out);
}

// round 7
// speedup vs baseline: 1.8186x; 1.0022x over previous
#include <cuda_runtime.h>
#include <math.h>

#define NBATCH 8
#define NPTS   256
#define NFEAT  32
#define NRBF_  50
#define NH     128
#define NK     255          // NPTS-1
#define SD     8960         // NPTS*3 + NPTS*32

// scratch (no allocations allowed)
__device__ float g_vx[NBATCH * NPTS * 3];
__device__ float g_tr[NBATCH * NPTS];

typedef unsigned long long u64;

__device__ __forceinline__ u64 pack2(float x, float y) {
  u64 r; asm("mov.b64 %0,{%1,%2};" : "=l"(r) : "f"(x), "f"(y)); return r;
}
__device__ __forceinline__ float2 unpack2(u64 v) {
  float2 f; asm("mov.b64 {%0,%1},%2;" : "=f"(f.x), "=f"(f.y) : "l"(v)); return f;
}
__device__ __forceinline__ u64 ffma2(u64 a, u64 b, u64 c) {
  u64 d; asm("fma.rn.f32x2 %0,%1,%2,%3;" : "=l"(d) : "l"(a), "l"(b), "l"(c)); return d;
}

// ---- shared memory layout (floats) ----
#define O_W1   0                    // 50*128 s1_W1 rbf block
#define O_WM   (O_W1 + 6400)        // mu[m]*s1_W1 (for d(z1)/dd = d*A1 - AM)
#define O_W2   (O_WM + 6400)        // s2_W1 rbf block
#define O_WF   (O_W2 + 6400)        // f_W1 rbf block
#define O_V21  (O_WF + 6400)        // 128 s1_W2
#define O_V22  (O_V21 + 128)        // 128 s2_W2
#define O_CF1  (O_V22 + 128)        // 128
#define O_CF2  (O_CF1 + 128)        // 128
#define O_CFF  (O_CF2 + 128)        // 128
#define O_XS   (O_CFF + 128)        // 768 positions
#define O_FS   (O_XS + 768)         // 32 feats
#define O_SMX  (O_FS + 32)          // 32 softmax(feats)
#define O_MUS  (O_SMX + 32)         // 64 (50 used)
#define O_HS   (O_MUS + 64)         // 4*128 per-warp silu(zf) sums
#define O_HT   (O_HS + 512)         // 128 totals
#define O_RED  (O_HT + 128)         // 4*8 reduction scratch
#define O_TOT  (O_RED + 32)         // 8 totals
#define SMEM_FLOATS (O_TOT + 8)     // 27816 floats = 111264 B

// per-hidden-lane epilogue for BOTH neighbors
#define EPI(A11, AM1, A21, AF1, A12, AM2, A22, AF2, C1, C2, CF, W21, W22, HIDX) do { \
    float z1a = (A11) + (C1);                                                 \
    float sga = __fdividef(1.f, 1.f + __expf(-z1a));                          \
    s1a1 = fmaf(z1a * sga, (W21), s1a1);                                      \
    float spa = sga * (1.f + z1a * (1.f - sga));                              \
    da1 = fmaf((W21) * spa, fmaf(d1, (A11), -(AM1)), da1);                    \
    float z1b = (A12) + (C1);                                                 \
    float sgb = __fdividef(1.f, 1.f + __expf(-z1b));                          \
    s1a2 = fmaf(z1b * sgb, (W21), s1a2);                                      \
    float spb = sgb * (1.f + z1b * (1.f - sgb));                              \
    da2 = fmaf((W21) * spb, fmaf(d2, (A12), -(AM2)), da2);                    \
    float z2a = (A21) + (C2);                                                 \
    float g2a = __fdividef(1.f, 1.f + __expf(-z2a));                          \
    s2a1 = fmaf(z2a * g2a, (W22), s2a1);                                      \
    float z2b = (A22) + (C2);                                                 \
    float g2b = __fdividef(1.f, 1.f + __expf(-z2b));                          \
    s2a2 = fmaf(z2b * g2b, (W22), s2a2);                                      \
    float zfa = (AF1) + (CF);                                                 \
    float gfa = __fdividef(1.f, 1.f + __expf(-zfa));                          \
    float zfb = (AF2) + (CF);                                                 \
    float gfb = __fdividef(1.f, 1.f + __expf(-zfb));                          \
    float slf = fmaf(zfb * gfb, act2, zfa * gfa);                             \
    _Pragma("unroll")                                                         \
    for (int o = 16; o; o >>= 1) slf += __shfl_xor_sync(0xffffffffu, slf, o); \
    if (lane == 0) smf[O_HS + wid * 128 + (HIDX)] += slf;                     \
  } while (0)

__global__ __launch_bounds__(128, 2) void fd_main(
    const float* __restrict__ state, const float* __restrict__ mus,
    const float* __restrict__ gamma_p,
    const float* __restrict__ s1W1, const float* __restrict__ s1b1,
    const float* __restrict__ s1W2, const float* __restrict__ s1b2,
    const float* __restrict__ s2W1, const float* __restrict__ s2b1,
    const float* __restrict__ s2W2, const float* __restrict__ s2b2,
    const float* __restrict__ fW1, const float* __restrict__ fb1,
    const float* __restrict__ fW2, const float* __restrict__ fb2,
    float* __restrict__ out)
{
  extern __shared__ float smf[];
  const int tid = threadIdx.x;
  const int wid = tid >> 5, lane = tid & 31;
  const int bi = blockIdx.x;
  const int b = bi >> 8;
  const int i = bi & 255;
  const float gam = gamma_p[0];

  // --- stage weights / inputs into smem ---
  for (int idx = tid; idx < 6400; idx += 128) {
    float w = s1W1[idx];
    smf[O_W1 + idx] = w;
    smf[O_WM + idx] = w * mus[idx >> 7];
    smf[O_W2 + idx] = s2W1[idx];
    smf[O_WF + idx] = fW1[idx];
  }
  smf[O_V21 + tid] = s1W2[tid];
  smf[O_V22 + tid] = s2W2[tid];
  for (int idx = tid; idx < 512; idx += 128) smf[O_HS + idx] = 0.f;
  for (int idx = tid; idx < 768; idx += 128) smf[O_XS + idx] = state[b * SD + idx];
  if (tid < 32) smf[O_FS + tid] = state[b * SD + 768 + i * 32 + tid];
  if (tid < 64) smf[O_MUS + tid] = (tid < NRBF_) ? mus[tid] : 0.f;
  __syncthreads();

  // softmax(feats) by warp 0
  if (tid < 32) {
    float v = smf[O_FS + tid];
    float mx = v;
    #pragma unroll
    for (int o = 16; o; o >>= 1) mx = fmaxf(mx, __shfl_xor_sync(0xffffffffu, mx, o));
    float e = __expf(v - mx);
    float s = e;
    #pragma unroll
    for (int o = 16; o; o >>= 1) s += __shfl_xor_sync(0xffffffffu, s, o);
    smf[O_SMX + tid] = __fdividef(e, s);
  }
  __syncthreads();

  // per-(b,i) constant hidden contributions (feat columns + bias), one lane per h
  {
    const int h = tid;
    float c1 = s1b1[h], c2 = s2b1[h], cf = fb1[h];
    #pragma unroll 4
    for (int f = 0; f < 32; f++) {
      float fv = smf[O_FS + f];
      c1 = fmaf(fv, s1W1[(50 + f) * 128 + h] + s1W1[(82 + f) * 128 + h], c1);
      c2 = fmaf(fv, s2W1[(50 + f) * 128 + h] + s2W1[(82 + f) * 128 + h], c2);
      cf = fmaf(smf[O_SMX + f], fW1[(50 + f) * 128 + h], cf);
    }
    smf[O_CF1 + h] = c1;
    smf[O_CF2 + h] = c2;
    smf[O_CFF + h] = cf;
  }
  __syncthreads();

  // --- each thread handles neighbors k1 = tid (always real) and k2 = tid+128 ---
  const int k1 = tid;
  const int k2t = tid + 128;
  const float act2 = (k2t < NK) ? 1.f : 0.f;
  const int k2 = (k2t < NK) ? k2t : NK - 1;
  const int j1 = (k1 < i) ? k1 : k1 + 1;
  const int j2 = (k2 < i) ? k2 : k2 + 1;
  const float xi0 = smf[O_XS + i * 3 + 0];
  const float xi1 = smf[O_XS + i * 3 + 1];
  const float xi2 = smf[O_XS + i * 3 + 2];
  const float rx1 = xi0 - smf[O_XS + j1 * 3 + 0];
  const float ry1 = xi1 - smf[O_XS + j1 * 3 + 1];
  const float rz1 = xi2 - smf[O_XS + j1 * 3 + 2];
  const float rx2 = xi0 - smf[O_XS + j2 * 3 + 0];
  const float ry2 = xi1 - smf[O_XS + j2 * 3 + 1];
  const float rz2 = xi2 - smf[O_XS + j2 * 3 + 2];
  const float rr1 = rx1 * rx1 + ry1 * ry1 + rz1 * rz1;
  const float rr2q = rx2 * rx2 + ry2 * ry2 + rz2 * rz2;
  const float d1 = sqrtf(rr1 + 1e-6f);
  const float d2 = sqrtf(rr2q + 1e-6f);

  float rbf1[NRBF_], rbf2[NRBF_];
  #pragma unroll
  for (int m = 0; m < NRBF_; m++) {
    float mu = smf[O_MUS + m];
    float dm1 = d1 - mu, dm2 = d2 - mu;
    rbf1[m] = __expf(-gam * dm1 * dm1);
    rbf2[m] = __expf(-gam * dm2 * dm2);
  }

  float s1a1 = 0.f, s1a2 = 0.f, s2a1 = 0.f, s2a2 = 0.f, da1 = 0.f, da2 = 0.f;

  #pragma unroll 1
  for (int hb = 0; hb < 128; hb += 4) {
    u64 A1a1 = 0ull, A1b1 = 0ull, A1a2 = 0ull, A1b2 = 0ull;
    u64 AMa1 = 0ull, AMb1 = 0ull, AMa2 = 0ull, AMb2 = 0ull;
    u64 A2a1 = 0ull, A2b1 = 0ull, A2a2 = 0ull, A2b2 = 0ull;
    u64 AFa1 = 0ull, AFb1 = 0ull, AFa2 = 0ull, AFb2 = 0ull;
    #pragma unroll
    for (int m = 0; m < NRBF_; m++) {
      const u64 rv1 = pack2(rbf1[m], rbf1[m]);
      const u64 rv2 = pack2(rbf2[m], rbf2[m]);
      const ulonglong2 w1 =
          *reinterpret_cast<const ulonglong2*>(&smf[O_W1 + m * 128 + hb]);
      A1a1 = ffma2(rv1, w1.x, A1a1);  A1b1 = ffma2(rv1, w1.y, A1b1);
      A1a2 = ffma2(rv2, w1.x, A1a2);  A1b2 = ffma2(rv2, w1.y, A1b2);
      const ulonglong2 wm =
          *reinterpret_cast<const ulonglong2*>(&smf[O_WM + m * 128 + hb]);
      AMa1 = ffma2(rv1, wm.x, AMa1);  AMb1 = ffma2(rv1, wm.y, AMb1);
      AMa2 = ffma2(rv2, wm.x, AMa2);  AMb2 = ffma2(rv2, wm.y, AMb2);
      const ulonglong2 w2 =
          *reinterpret_cast<const ulonglong2*>(&smf[O_W2 + m * 128 + hb]);
      A2a1 = ffma2(rv1, w2.x, A2a1);  A2b1 = ffma2(rv1, w2.y, A2b1);
      A2a2 = ffma2(rv2, w2.x, A2a2);  A2b2 = ffma2(rv2, w2.y, A2b2);
      const ulonglong2 wf =
          *reinterpret_cast<const ulonglong2*>(&smf[O_WF + m * 128 + hb]);
      AFa1 = ffma2(rv1, wf.x, AFa1);  AFb1 = ffma2(rv1, wf.y, AFb1);
      AFa2 = ffma2(rv2, wf.x, AFa2);  AFb2 = ffma2(rv2, wf.y, AFb2);
    }
    const float2 a1lo1 = unpack2(A1a1), a1hi1 = unpack2(A1b1);
    const float2 a1lo2 = unpack2(A1a2), a1hi2 = unpack2(A1b2);
    const float2 amlo1 = unpack2(AMa1), amhi1 = unpack2(AMb1);
    const float2 amlo2 = unpack2(AMa2), amhi2 = unpack2(AMb2);
    const float2 a2lo1 = unpack2(A2a1), a2hi1 = unpack2(A2b1);
    const float2 a2lo2 = unpack2(A2a2), a2hi2 = unpack2(A2b2);
    const float2 aflo1 = unpack2(AFa1), afhi1 = unpack2(AFb1);
    const float2 aflo2 = unpack2(AFa2), afhi2 = unpack2(AFb2);
    const float4 c1v = *reinterpret_cast<const float4*>(&smf[O_CF1 + hb]);
    const float4 c2v = *reinterpret_cast<const float4*>(&smf[O_CF2 + hb]);
    const float4 cfv = *reinterpret_cast<const float4*>(&smf[O_CFF + hb]);
    const float4 w21 = *reinterpret_cast<const float4*>(&smf[O_V21 + hb]);
    const float4 w22 = *reinterpret_cast<const float4*>(&smf[O_V22 + hb]);
    EPI(a1lo1.x, amlo1.x, a2lo1.x, aflo1.x, a1lo2.x, amlo2.x, a2lo2.x, aflo2.x,
        c1v.x, c2v.x, cfv.x, w21.x, w22.x, hb + 0);
    EPI(a1lo1.y, amlo1.y, a2lo1.y, aflo1.y, a1lo2.y, amlo2.y, a2lo2.y, aflo2.y,
        c1v.y, c2v.y, cfv.y, w21.y, w22.y, hb + 1);
    EPI(a1hi1.x, amhi1.x, a2hi1.x, afhi1.x, a1hi2.x, amhi2.x, a2hi2.x, afhi2.x,
        c1v.z, c2v.z, cfv.z, w21.z, w22.z, hb + 2);
    EPI(a1hi1.y, amhi1.y, a2hi1.y, afhi1.y, a1hi2.y, amhi2.y, a2hi2.y, afhi2.y,
        c1v.w, c2v.w, cfv.w, w21.w, w22.w, hb + 3);
  }

  // --- per-thread scalar outputs, both neighbors folded together ---
  const float b2s1 = s1b2[0], b2s2 = s2b2[0];
  const float s1v1 = s1a1 + b2s1;
  const float s2v1 = s2a1 + b2s2;
  const float gd1 = -2.f * gam * da1 * __fdividef(rr1, d1);
  const float s1v2 = (s1a2 + b2s1) * act2;
  const float s2v2 = (s2a2 + b2s2) * act2;
  const float gd2 = -2.f * gam * da2 * __fdividef(rr2q, d2) * act2;

  float vals[7];
  vals[0] = fmaf(s1v2, rx2, s1v1 * rx1);
  vals[1] = fmaf(s1v2, ry2, s1v1 * ry1);
  vals[2] = fmaf(s1v2, rz2, s1v1 * rz1);
  vals[3] = fmaf(s2v2, rx2, s2v1 * rx1);
  vals[4] = fmaf(s2v2, ry2, s2v1 * ry1);
  vals[5] = fmaf(s2v2, rz2, s2v1 * rz1);
  vals[6] = gd1 + 3.f * s1v1 + gd2 + 3.f * s1v2;

  // --- block reduction over neighbors (7 values, 4 warps) ---
  #pragma unroll
  for (int c = 0; c < 7; c++) {
    float v = vals[c];
    #pragma unroll
    for (int o = 16; o; o >>= 1) v += __shfl_xor_sync(0xffffffffu, v, o);
    vals[c] = v;
  }
  if (lane == 0) {
    #pragma unroll
    for (int c = 0; c < 7; c++) smf[O_RED + wid * 8 + c] = vals[c];
  }
  __syncthreads();
  if (tid < 7) {
    float s = 0.f;
    #pragma unroll
    for (int w = 0; w < 4; w++) s += smf[O_RED + w * 8 + tid];
    smf[O_TOT + tid] = s;
  }
  // cross-warp reduce of per-warp silu(zf) hidden sums
  {
    float s = 0.f;
    #pragma unroll
    for (int w = 0; w < 4; w++) s += smf[O_HS + w * 128 + tid];
    smf[O_HT + tid] = s;
  }
  __syncthreads();

  if (tid == 0) {
    const float inv = 1.f / (float)NK;
    const float v1x = smf[O_TOT + 0] * inv;
    const float v1y = smf[O_TOT + 1] * inv;
    const float v1z = smf[O_TOT + 2] * inv;
    const float m2x = smf[O_TOT + 3] * inv;
    const float m2y = smf[O_TOT + 4] * inv;
    const float m2z = smf[O_TOT + 5] * inv;
    // mean_k( s2 * (r x v1) ) = (mean_k s2*r) x v1
    const float cxx = m2y * v1z - m2z * v1y;
    const float cxy = m2z * v1x - m2x * v1z;
    const float cxz = m2x * v1y - m2y * v1x;
    g_vx[bi * 3 + 0] = v1x + cxx;
    g_vx[bi * 3 + 1] = v1y + cxy;
    g_vx[bi * 3 + 2] = v1z + cxz;
    g_tr[bi] = smf[O_TOT + 6];
  }
  // v_feats = (mean_k silu(zf)) @ fW2 + fb2   (fW2 linear -> commutes with mean)
  if (tid < 32) {
    float acc = 0.f;
    #pragma unroll 8
    for (int h = 0; h < 128; h++) acc = fmaf(smf[O_HT + h], fW2[h * 32 + tid], acc);
    out[b * SD + 768 + i * 32 + tid] = acc * (1.f / (float)NK) + fb2[tid];
  }
}

__global__ __launch_bounds__(256) void fd_final(float* __restrict__ out)
{
  __shared__ float red[8][4];
  __shared__ float tot[4];
  const int b = blockIdx.x;
  const int tid = threadIdx.x;

  const float v0 = g_vx[(b * NPTS + tid) * 3 + 0];
  const float v1 = g_vx[(b * NPTS + tid) * 3 + 1];
  const float v2 = g_vx[(b * NPTS + tid) * 3 + 2];
  const float v3 = g_tr[b * NPTS + tid];

  float r0 = v0, r1 = v1, r2 = v2, r3 = v3;
  #pragma unroll
  for (int o = 16; o; o >>= 1) {
    r0 += __shfl_xor_sync(0xffffffffu, r0, o);
    r1 += __shfl_xor_sync(0xffffffffu, r1, o);
    r2 += __shfl_xor_sync(0xffffffffu, r2, o);
    r3 += __shfl_xor_sync(0xffffffffu, r3, o);
  }
  const int wid = tid >> 5, lane = tid & 31;
  if (lane == 0) { red[wid][0] = r0; red[wid][1] = r1; red[wid][2] = r2; red[wid][3] = r3; }
  __syncthreads();
  if (tid < 4) {
    float s = 0.f;
    #pragma unroll
    for (int w = 0; w < 8; w++) s += red[w][tid];
    tot[tid] = s;
  }
  __syncthreads();

  const float invn = 1.f / (float)NPTS;
  out[b * SD + tid * 3 + 0] = v0 - tot[0] * invn;
  out[b * SD + tid * 3 + 1] = v1 - tot[1] * invn;
  out[b * SD + tid * 3 + 2] = v2 - tot[2] * invn;
  if (tid == 0) out[NBATCH * SD + b] = tot[3] * (1.f / (float)NK);
}

extern "C" void kernel_launch(void* const* d_in, const int* in_sizes, int n_in,
                              void* d_out, int out_size)
{
  const float* state = (const float*)d_in[1];
  const float* mus   = (const float*)d_in[2];
  const float* gam   = (const float*)d_in[3];
  const float* s1W1  = (const float*)d_in[4];
  const float* s1b1  = (const float*)d_in[5];
  const float* s1W2  = (const float*)d_in[6];
  const float* s1b2  = (const float*)d_in[7];
  const float* s2W1  = (const float*)d_in[8];
  const float* s2b1  = (const float*)d_in[9];
  const float* s2W2  = (const float*)d_in[10];
  const float* s2b2  = (const float*)d_in[11];
  const float* fW1   = (const float*)d_in[12];
  const float* fb1   = (const float*)d_in[13];
  const float* fW2   = (const float*)d_in[14];
  const float* fb2   = (const float*)d_in[15];
  float* out = (float*)d_out;

  const int smem_bytes = SMEM_FLOATS * (int)sizeof(float);
  cudaFuncSetAttribute(fd_main, cudaFuncAttributeMaxDynamicSharedMemorySize, smem_bytes);

  fd_main<<<NBATCH * NPTS, 128, smem_bytes>>>(
      state, mus, gam,
      s1W1, s1b1, s1W2, s1b2,
      s2W1, s2b1, s2W2, s2b2,
      fW1, fb1, fW2, fb2, out);
  fd_final<<<NBATCH, 256>>>(out);
}